// round 2
// baseline (speedup 1.0000x reference)
#include <cuda_runtime.h>
#include <math.h>

#define T_STEPS 128
#define B_ENV   256
#define N_TOT   (T_STEPS * B_ENV)   // 32768
#define HID     128
#define NFLAT   1024
#define NG      512                  // 4*HID

// -------- scratch (static device arrays; no allocation) --------
__device__ float g_feat [N_TOT * NFLAT];   // 128 MB
__device__ float g_gatex[N_TOT * NG];      // 64 MB
__device__ float g_whhT [HID * NG];        // 256 KB, k-major transpose of w_hh
__device__ float g_hid  [N_TOT * HID];     // 16 MB

// ============================================================
// Kernel 0: transpose w_hh [512,128] -> w_hhT [128,512]
// ============================================================
__global__ void k_transpose_whh(const float* __restrict__ whh) {
    int idx = blockIdx.x * blockDim.x + threadIdx.x;   // 65536 total
    if (idx < NG * HID) {
        int k = idx >> 9;        // idx = k*512 + j
        int j = idx & 511;
        g_whhT[idx] = whh[j * HID + k];
    }
}

// ============================================================
// Kernel 1: fused conv stack (7x7x3 -> 6x6x16 -> 5x5x32 -> 4x4x64)
// one sample per warp, 8 samples per block, weights in smem
// ============================================================
#define CONV_WSM 10544   // 192+16+2048+32+8192+64
#define CONV_PW  1523    // per-warp scratch floats: obs 147 + x1 576 + x2 800

__global__ void k_conv(const float* __restrict__ obs,
                       const float* __restrict__ w1, const float* __restrict__ b1,
                       const float* __restrict__ w2, const float* __restrict__ b2,
                       const float* __restrict__ w3, const float* __restrict__ b3) {
    extern __shared__ float sm[];
    float* W1 = sm;
    float* B1 = sm + 192;
    float* W2 = sm + 208;
    float* B2 = sm + 2256;
    float* W3 = sm + 2288;
    float* B3 = sm + 10480;
    int tid = threadIdx.x;
    for (int i = tid; i < 192;  i += 256) W1[i] = w1[i];
    for (int i = tid; i < 16;   i += 256) B1[i] = b1[i];
    for (int i = tid; i < 2048; i += 256) W2[i] = w2[i];
    for (int i = tid; i < 32;   i += 256) B2[i] = b2[i];
    for (int i = tid; i < 8192; i += 256) W3[i] = w3[i];
    for (int i = tid; i < 64;   i += 256) B3[i] = b3[i];
    __syncthreads();

    int warp = tid >> 5, lane = tid & 31;
    int n = blockIdx.x * 8 + warp;            // grid = 4096 -> n < 32768
    float* buf = sm + CONV_WSM + warp * CONV_PW;
    float* O  = buf;          // obs  [7][7][3] HWC
    float* X1 = buf + 147;    // [16][6][6]
    float* X2 = buf + 723;    // [32][5][5]

    const float* op = obs + (size_t)n * 147;
    for (int i = lane; i < 147; i += 32) O[i] = op[i];
    __syncwarp();

    // conv1: 16 x 6 x 6, taps 2x2, cin=3
    for (int idx = lane; idx < 576; idx += 32) {
        int co = idx / 36, pos = idx % 36, y = pos / 6, x = pos % 6;
        const float* w = W1 + co * 12;
        float a = B1[co];
        #pragma unroll
        for (int ci = 0; ci < 3; ci++) {
            a += O[(y * 7 + x) * 3 + ci]           * w[ci * 4 + 0];
            a += O[(y * 7 + x + 1) * 3 + ci]       * w[ci * 4 + 1];
            a += O[((y + 1) * 7 + x) * 3 + ci]     * w[ci * 4 + 2];
            a += O[((y + 1) * 7 + x + 1) * 3 + ci] * w[ci * 4 + 3];
        }
        X1[co * 36 + pos] = fmaxf(a, 0.f);
    }
    __syncwarp();

    // conv2: 32 x 5 x 5, cin=16
    for (int idx = lane; idx < 800; idx += 32) {
        int co = idx / 25, pos = idx % 25, y = pos / 5, x = pos % 5;
        const float* w = W2 + co * 64;
        float a = B2[co];
        #pragma unroll
        for (int ci = 0; ci < 16; ci++) {
            const float* xp = X1 + ci * 36 + y * 6 + x;
            const float* wp = w + ci * 4;
            a += xp[0] * wp[0] + xp[1] * wp[1] + xp[6] * wp[2] + xp[7] * wp[3];
        }
        X2[co * 25 + pos] = fmaxf(a, 0.f);
    }
    __syncwarp();

    // conv3: 64 x 4 x 4, cin=32 -> feat (NCHW flatten: c*16 + y*4 + x)
    float* outp = g_feat + (size_t)n * NFLAT;
    for (int idx = lane; idx < 1024; idx += 32) {
        int co = idx >> 4, y = (idx >> 2) & 3, x = idx & 3;
        const float* w = W3 + co * 128;
        float a = B3[co];
        #pragma unroll
        for (int ci = 0; ci < 32; ci++) {
            const float* xp = X2 + ci * 25 + y * 5 + x;
            const float* wp = w + ci * 4;
            a += xp[0] * wp[0] + xp[1] * wp[1] + xp[5] * wp[2] + xp[6] * wp[3];
        }
        outp[idx] = fmaxf(a, 0.f);
    }
}

// ============================================================
// Kernel 2: gate_x = feat @ w_ih^T + (b_ih + b_hh)
// [32768,1024] x [1024,512] tiled SIMT fp32 GEMM, BM=128 BN=64 BK=16
// ============================================================
__global__ void k_gemm_ih(const float* __restrict__ wih,
                          const float* __restrict__ bih,
                          const float* __restrict__ bhh) {
    __shared__ float As[16][128];
    __shared__ float Bs[16][64];
    int tid = threadIdx.x;
    int row0 = blockIdx.x * 128;
    int col0 = blockIdx.y * 64;
    int ty = tid >> 4, tx = tid & 15;   // ty: 8-row group, tx: 4-col group

    float acc[8][4];
    #pragma unroll
    for (int i = 0; i < 8; i++)
        #pragma unroll
        for (int j = 0; j < 4; j++) acc[i][j] = 0.f;

    for (int k0 = 0; k0 < 1024; k0 += 16) {
        #pragma unroll
        for (int li = 0; li < 2; li++) {
            int lin = tid + li * 256;
            int r = lin >> 2, kq = (lin & 3) * 4;
            float4 v = *(const float4*)&g_feat[(size_t)(row0 + r) * 1024 + k0 + kq];
            As[kq + 0][r] = v.x; As[kq + 1][r] = v.y;
            As[kq + 2][r] = v.z; As[kq + 3][r] = v.w;
        }
        {
            int j = tid >> 2, kq = (tid & 3) * 4;
            float4 v = *(const float4*)&wih[(size_t)(col0 + j) * 1024 + k0 + kq];
            Bs[kq + 0][j] = v.x; Bs[kq + 1][j] = v.y;
            Bs[kq + 2][j] = v.z; Bs[kq + 3][j] = v.w;
        }
        __syncthreads();
        #pragma unroll
        for (int kk = 0; kk < 16; kk++) {
            float a[8], b[4];
            #pragma unroll
            for (int i = 0; i < 8; i++) a[i] = As[kk][ty * 8 + i];
            #pragma unroll
            for (int j = 0; j < 4; j++) b[j] = Bs[kk][tx * 4 + j];
            #pragma unroll
            for (int i = 0; i < 8; i++)
                #pragma unroll
                for (int j = 0; j < 4; j++) acc[i][j] += a[i] * b[j];
        }
        __syncthreads();
    }
    #pragma unroll
    for (int j = 0; j < 4; j++) {
        int c = col0 + tx * 4 + j;
        float bias = bih[c] + bhh[c];
        #pragma unroll
        for (int i = 0; i < 8; i++) {
            int n = row0 + ty * 8 + i;
            g_gatex[(size_t)n * NG + c] = acc[i][j] + bias;
        }
    }
}

// ============================================================
// Kernel 3: persistent LSTM scan. 128 blocks x 2 envs, 256 threads.
// thread t owns gates (2t, 2t+1). w_hhT rows 0..KS-1 smem-resident,
// rows KS..127 streamed from L2 each step.
// ============================================================
#define KS 110
#define SCAN_SMEM_FLOATS (KS * 512 + 256 + 256 + 1024)

__global__ void k_scan(const float* __restrict__ done,
                       const float* __restrict__ h0,
                       const float* __restrict__ c0,
                       float* __restrict__ dout) {
    extern __shared__ float sm[];
    float* Ws = sm;                      // [KS][512]
    float* hs = sm + KS * 512;           // [2][128]
    float* cs = hs + 256;                // [2][128]
    float* gs = cs + 256;                // [2][512] activated gates

    int tid = threadIdx.x;
    int e0 = blockIdx.x * 2;

    for (int i = tid; i < KS * 512; i += 256) Ws[i] = g_whhT[i];
    {
        int e = tid >> 7, m = tid & 127;
        int env = e0 + e;
        float s = 1.f - done[env];        // t = 0 mask
        hs[tid] = h0[env * HID + m] * s;
        cs[tid] = c0[env * HID + m] * s;
    }
    __syncthreads();

    int j0 = tid * 2;
    int gtype = tid >> 6;   // 0:i 1:f 2:g 3:o

    for (int t = 0; t < T_STEPS; t++) {
        #pragma unroll
        for (int e = 0; e < 2; e++) {
            int env = e0 + e;
            const float* gx = g_gatex + (size_t)(t * B_ENV + env) * NG;
            float2 a0 = *(const float2*)&gx[j0];
            float acc0 = a0.x, acc1 = a0.y;
            const float* hp = hs + e * HID;
            const float* wp = Ws + j0;
            #pragma unroll 10
            for (int k = 0; k < KS; k++) {
                float2 w = *(const float2*)wp;
                float hv = hp[k];
                acc0 += w.x * hv;
                acc1 += w.y * hv;
                wp += 512;
            }
            const float* wg = g_whhT + KS * 512 + j0;
            #pragma unroll
            for (int k = KS; k < HID; k++) {
                float2 w = __ldg((const float2*)wg);
                float hv = hp[k];
                acc0 += w.x * hv;
                acc1 += w.y * hv;
                wg += 512;
            }
            if (gtype == 2) {
                acc0 = tanhf(acc0);
                acc1 = tanhf(acc1);
            } else {
                acc0 = 1.f / (1.f + __expf(-acc0));
                acc1 = 1.f / (1.f + __expf(-acc1));
            }
            gs[e * 512 + j0]     = acc0;
            gs[e * 512 + j0 + 1] = acc1;
        }
        __syncthreads();
        {
            int e = tid >> 7, m = tid & 127, env = e0 + e;
            const float* G = gs + e * 512;
            float c = G[128 + m] * cs[tid] + G[m] * G[256 + m];
            float h = G[384 + m] * tanhf(c);
            g_hid[(size_t)(t * B_ENV + env) * HID + m] = h;
            if (t < T_STEPS - 1) {
                float s = 1.f - done[(t + 1) * B_ENV + env];
                hs[tid] = h * s;
                cs[tid] = c * s;
            } else {
                hs[tid] = h;
                cs[tid] = c;
            }
        }
        __syncthreads();
    }

    // hT / cT tails of output
    {
        int e = tid >> 7, m = tid & 127, env = e0 + e;
        dout[262144 + env * HID + m]         = hs[tid];
        dout[262144 + 32768 + env * HID + m] = cs[tid];
    }
}

// ============================================================
// Kernel 4: heads — out[n, 0:7] = actor, out[n, 7] = value
// ============================================================
__global__ void k_head(const float* __restrict__ aw, const float* __restrict__ ab,
                       const float* __restrict__ cw, const float* __restrict__ cb,
                       float* __restrict__ dout) {
    __shared__ float Hs[32 * 128];
    __shared__ float Wsm[8 * 128];
    __shared__ float Bsm[8];
    int tid = threadIdx.x;
    for (int i = tid; i < 896; i += 256) Wsm[i] = aw[i];
    for (int i = tid; i < 128; i += 256) Wsm[896 + i] = cw[i];
    if (tid < 7) Bsm[tid] = ab[tid];
    if (tid == 7) Bsm[7] = cb[0];
    int n0 = blockIdx.x * 32;
    for (int i = tid; i < 4096; i += 256) Hs[i] = g_hid[(size_t)n0 * 128 + i];
    __syncthreads();
    int r = tid >> 3, o = tid & 7;
    const float* h = Hs + r * 128;
    const float* w = Wsm + o * 128;
    float a = Bsm[o];
    #pragma unroll
    for (int k = 0; k < 128; k++) a += h[k] * w[k];
    dout[(size_t)(n0 + r) * 8 + o] = a;
}

// ============================================================
extern "C" void kernel_launch(void* const* d_in, const int* in_sizes, int n_in,
                              void* d_out, int out_size) {
    const float* obs  = (const float*)d_in[0];
    const float* done = (const float*)d_in[1];
    const float* h0   = (const float*)d_in[2];
    const float* c0   = (const float*)d_in[3];
    const float* w1   = (const float*)d_in[4];
    const float* b1   = (const float*)d_in[5];
    const float* w2   = (const float*)d_in[6];
    const float* b2   = (const float*)d_in[7];
    const float* w3   = (const float*)d_in[8];
    const float* b3   = (const float*)d_in[9];
    const float* wih  = (const float*)d_in[10];
    const float* whh  = (const float*)d_in[11];
    const float* bih  = (const float*)d_in[12];
    const float* bhh  = (const float*)d_in[13];
    const float* aw   = (const float*)d_in[14];
    const float* ab   = (const float*)d_in[15];
    const float* cw   = (const float*)d_in[16];
    const float* cb   = (const float*)d_in[17];
    float* out = (float*)d_out;

    cudaFuncSetAttribute(k_conv, cudaFuncAttributeMaxDynamicSharedMemorySize,
                         (CONV_WSM + 8 * CONV_PW) * 4);
    cudaFuncSetAttribute(k_scan, cudaFuncAttributeMaxDynamicSharedMemorySize,
                         SCAN_SMEM_FLOATS * 4);

    k_transpose_whh<<<256, 256>>>(whh);
    k_conv<<<4096, 256, (CONV_WSM + 8 * CONV_PW) * 4>>>(obs, w1, b1, w2, b2, w3, b3);
    dim3 gg(256, 8);
    k_gemm_ih<<<gg, 256>>>(wih, bih, bhh);
    k_scan<<<128, 256, SCAN_SMEM_FLOATS * 4>>>(done, h0, c0, out);
    k_head<<<1024, 256>>>(aw, ab, cw, cb, out);
}

// round 4
// speedup vs baseline: 1.4733x; 1.4733x over previous
#include <cuda_runtime.h>
#include <cuda_bf16.h>
#include <math.h>
#include <stdint.h>

#define T_STEPS 128
#define B_ENV   256
#define N_TOT   (T_STEPS * B_ENV)   // 32768
#define HID     128
#define NFLAT   1024
#define NG      512                  // 4*HID

// -------- scratch (static device arrays; no allocation) --------
__device__ float g_gatex[N_TOT * NG];            // 64 MB
__device__ float g_whhT [HID * NG];              // 256 KB
__device__ float g_hid  [N_TOT * HID];           // 16 MB
__device__ __nv_bfloat16 g_featH[N_TOT * NFLAT]; // 64 MB
__device__ __nv_bfloat16 g_featL[N_TOT * NFLAT]; // 64 MB
__device__ __nv_bfloat16 g_wihH [NG * NFLAT];    // 1 MB
__device__ __nv_bfloat16 g_wihL [NG * NFLAT];    // 1 MB

// ================= helpers =================
__device__ __forceinline__ uint32_t s2u(const void* p) {
    uint32_t a;
    asm("{ .reg .u64 t; cvta.to.shared.u64 t, %1; cvt.u32.u64 %0, t; }"
        : "=r"(a) : "l"(p));
    return a;
}
__device__ __forceinline__ void ldsm4(uint32_t* r, uint32_t addr) {
    asm volatile("ldmatrix.sync.aligned.m8n8.x4.shared.b16 {%0,%1,%2,%3}, [%4];"
                 : "=r"(r[0]), "=r"(r[1]), "=r"(r[2]), "=r"(r[3]) : "r"(addr));
}
__device__ __forceinline__ void mma16816(float* d, const uint32_t* a, const uint32_t* b) {
    asm volatile(
        "mma.sync.aligned.m16n8k16.row.col.f32.bf16.bf16.f32 "
        "{%0,%1,%2,%3}, {%4,%5,%6,%7}, {%8,%9}, {%0,%1,%2,%3};"
        : "+f"(d[0]), "+f"(d[1]), "+f"(d[2]), "+f"(d[3])
        : "r"(a[0]), "r"(a[1]), "r"(a[2]), "r"(a[3]), "r"(b[0]), "r"(b[1]));
}
#define CPA16(dst, src) \
    asm volatile("cp.async.cg.shared.global [%0], [%1], 16;" :: "r"(dst), "l"(src))

// ============================================================
// Kernel 0a: transpose w_hh [512,128] -> w_hhT [128,512]
// ============================================================
__global__ void k_transpose_whh(const float* __restrict__ whh) {
    int idx = blockIdx.x * blockDim.x + threadIdx.x;
    if (idx < NG * HID) {
        int k = idx >> 9;
        int j = idx & 511;
        g_whhT[idx] = whh[j * HID + k];
    }
}

// ============================================================
// Kernel 0b: split w_ih into bf16 hi/lo
// ============================================================
__global__ void k_split_wih(const float* __restrict__ wih) {
    int idx = blockIdx.x * blockDim.x + threadIdx.x;
    if (idx < NG * NFLAT) {
        float v = wih[idx];
        __nv_bfloat16 h = __float2bfloat16(v);
        g_wihH[idx] = h;
        g_wihL[idx] = __float2bfloat16(v - __bfloat162float(h));
    }
}

// ============================================================
// Kernel 1: fused conv stack -> feat written as bf16 hi/lo split
// ============================================================
#define CONV_WSM 10544
#define CONV_PW  1523

__global__ void k_conv(const float* __restrict__ obs,
                       const float* __restrict__ w1, const float* __restrict__ b1,
                       const float* __restrict__ w2, const float* __restrict__ b2,
                       const float* __restrict__ w3, const float* __restrict__ b3) {
    extern __shared__ float sm[];
    float* W1 = sm;
    float* B1 = sm + 192;
    float* W2 = sm + 208;
    float* B2 = sm + 2256;
    float* W3 = sm + 2288;
    float* B3 = sm + 10480;
    int tid = threadIdx.x;
    for (int i = tid; i < 192;  i += 256) W1[i] = w1[i];
    for (int i = tid; i < 16;   i += 256) B1[i] = b1[i];
    for (int i = tid; i < 2048; i += 256) W2[i] = w2[i];
    for (int i = tid; i < 32;   i += 256) B2[i] = b2[i];
    for (int i = tid; i < 8192; i += 256) W3[i] = w3[i];
    for (int i = tid; i < 64;   i += 256) B3[i] = b3[i];
    __syncthreads();

    int warp = tid >> 5, lane = tid & 31;
    int n = blockIdx.x * 8 + warp;
    float* buf = sm + CONV_WSM + warp * CONV_PW;
    float* O  = buf;
    float* X1 = buf + 147;
    float* X2 = buf + 723;

    const float* op = obs + (size_t)n * 147;
    for (int i = lane; i < 147; i += 32) O[i] = op[i];
    __syncwarp();

    for (int idx = lane; idx < 576; idx += 32) {
        int co = idx / 36, pos = idx % 36, y = pos / 6, x = pos % 6;
        const float* w = W1 + co * 12;
        float a = B1[co];
        #pragma unroll
        for (int ci = 0; ci < 3; ci++) {
            a += O[(y * 7 + x) * 3 + ci]           * w[ci * 4 + 0];
            a += O[(y * 7 + x + 1) * 3 + ci]       * w[ci * 4 + 1];
            a += O[((y + 1) * 7 + x) * 3 + ci]     * w[ci * 4 + 2];
            a += O[((y + 1) * 7 + x + 1) * 3 + ci] * w[ci * 4 + 3];
        }
        X1[co * 36 + pos] = fmaxf(a, 0.f);
    }
    __syncwarp();

    for (int idx = lane; idx < 800; idx += 32) {
        int co = idx / 25, pos = idx % 25, y = pos / 5, x = pos % 5;
        const float* w = W2 + co * 64;
        float a = B2[co];
        #pragma unroll
        for (int ci = 0; ci < 16; ci++) {
            const float* xp = X1 + ci * 36 + y * 6 + x;
            const float* wp = w + ci * 4;
            a += xp[0] * wp[0] + xp[1] * wp[1] + xp[6] * wp[2] + xp[7] * wp[3];
        }
        X2[co * 25 + pos] = fmaxf(a, 0.f);
    }
    __syncwarp();

    __nv_bfloat16* oh = g_featH + (size_t)n * NFLAT;
    __nv_bfloat16* ol = g_featL + (size_t)n * NFLAT;
    for (int idx = lane; idx < 1024; idx += 32) {
        int co = idx >> 4, y = (idx >> 2) & 3, x = idx & 3;
        const float* w = W3 + co * 128;
        float a = B3[co];
        #pragma unroll
        for (int ci = 0; ci < 32; ci++) {
            const float* xp = X2 + ci * 25 + y * 5 + x;
            const float* wp = w + ci * 4;
            a += xp[0] * wp[0] + xp[1] * wp[1] + xp[5] * wp[2] + xp[6] * wp[3];
        }
        float v = fmaxf(a, 0.f);
        __nv_bfloat16 h = __float2bfloat16(v);
        oh[idx] = h;
        ol[idx] = __float2bfloat16(v - __bfloat162float(h));
    }
}

// ============================================================
// Kernel 2: split-bf16 GEMM via mma.sync (HMMA tensor path)
// gate_x[32768,512] = feat @ w_ih^T + bias
// BM=128 BN=64 BK=32, 8 warps (4m x 2n), warp tile 32x32.
// D = Ah@Bh + Ah@Bl + Al@Bh, fp32 accumulators.
// smem rows padded to 80B (40 bf16) -> conflict-free ldmatrix.
// ============================================================
#define RS 80                       // row stride bytes
#define G_AH(buf) (256 + (buf) * 30720)
#define G_AL(buf) (G_AH(buf) + 10240)
#define G_BH(buf) (G_AH(buf) + 20480)
#define G_BL(buf) (G_AH(buf) + 25600)
#define G_TOT (256 + 2 * 30720)     // 61696 bytes

__global__ void __launch_bounds__(256, 2)
k_gemm_mma(const float* __restrict__ bih, const float* __restrict__ bhh) {
    extern __shared__ char smc[];
    uint32_t sb = s2u(smc);
    float* biasS = (float*)smc;
    int tid = threadIdx.x, wid = tid >> 5, lane = tid & 31;
    int m0 = blockIdx.x * 128, c0b = blockIdx.y * 64;
    int warp_m = (wid & 3) * 32, warp_n = (wid >> 2) * 32;

    for (int i = tid; i < 64; i += 256) biasS[i] = bih[c0b + i] + bhh[c0b + i];

    // lane-fixed ldmatrix source offsets
    int aRow = lane & 15;
    int aKb  = (lane >> 4) * 16;
    int bN   = (lane & 7) + ((lane >> 4) << 3);
    int bKb  = ((lane >> 3) & 1) * 16;

    float acc[2][4][4];
    #pragma unroll
    for (int i = 0; i < 2; i++)
        #pragma unroll
        for (int j = 0; j < 4; j++)
            #pragma unroll
            for (int q = 0; q < 4; q++) acc[i][j][q] = 0.f;

    // cp.async task decomposition
    int arow = tid >> 1, aseg2 = (tid & 1) * 2;       // A: 128 rows x 4 segs, 2/thread x2
    int brow = tid >> 2, bseg = tid & 3;              // B: 64 rows x 4 segs, 1/thread

    auto load_chunk = [&](int ch, int buf) {
        int k0 = ch * 32;
        const __nv_bfloat16* fH = g_featH + (size_t)(m0 + arow) * 1024 + k0 + aseg2 * 8;
        const __nv_bfloat16* fL = g_featL + (size_t)(m0 + arow) * 1024 + k0 + aseg2 * 8;
        uint32_t da = sb + G_AH(buf) + arow * RS + aseg2 * 16;
        uint32_t dal = sb + G_AL(buf) + arow * RS + aseg2 * 16;
        CPA16(da, fH);      CPA16(da + 16, fH + 8);
        CPA16(dal, fL);     CPA16(dal + 16, fL + 8);
        const __nv_bfloat16* wH = g_wihH + (size_t)(c0b + brow) * 1024 + k0 + bseg * 8;
        const __nv_bfloat16* wL = g_wihL + (size_t)(c0b + brow) * 1024 + k0 + bseg * 8;
        CPA16(sb + G_BH(buf) + brow * RS + bseg * 16, wH);
        CPA16(sb + G_BL(buf) + brow * RS + bseg * 16, wL);
    };

    load_chunk(0, 0);
    asm volatile("cp.async.commit_group;");

    const int NC = 32;
    for (int ch = 0; ch < NC; ch++) {
        int buf = ch & 1;
        if (ch + 1 < NC) {
            load_chunk(ch + 1, buf ^ 1);
            asm volatile("cp.async.commit_group;");
            asm volatile("cp.async.wait_group 1;");
        } else {
            asm volatile("cp.async.wait_group 0;");
        }
        __syncthreads();

        uint32_t aBh = sb + G_AH(buf) + (warp_m + aRow) * RS + aKb;
        uint32_t aBl = sb + G_AL(buf) + (warp_m + aRow) * RS + aKb;
        uint32_t bBh = sb + G_BH(buf) + (warp_n + bN) * RS + bKb;
        uint32_t bBl = sb + G_BL(buf) + (warp_n + bN) * RS + bKb;

        #pragma unroll
        for (int ks = 0; ks < 2; ks++) {
            uint32_t ah[2][4], al[2][4], bh[2][4], bl[2][4];
            #pragma unroll
            for (int mt = 0; mt < 2; mt++) {
                ldsm4(ah[mt], aBh + mt * 16 * RS + ks * 32);
                ldsm4(al[mt], aBl + mt * 16 * RS + ks * 32);
            }
            #pragma unroll
            for (int nt = 0; nt < 2; nt++) {
                ldsm4(bh[nt], bBh + nt * 16 * RS + ks * 32);
                ldsm4(bl[nt], bBl + nt * 16 * RS + ks * 32);
            }
            #pragma unroll
            for (int mt = 0; mt < 2; mt++)
                #pragma unroll
                for (int nt = 0; nt < 2; nt++)
                    #pragma unroll
                    for (int f = 0; f < 2; f++) {
                        float* d = acc[mt][nt * 2 + f];
                        mma16816(d, ah[mt], &bh[nt][f * 2]);
                        mma16816(d, ah[mt], &bl[nt][f * 2]);
                        mma16816(d, al[mt], &bh[nt][f * 2]);
                    }
        }
        __syncthreads();
    }

    // epilogue
    int r0 = lane >> 2, cpair = (lane & 3) * 2;
    #pragma unroll
    for (int mt = 0; mt < 2; mt++) {
        #pragma unroll
        for (int nI = 0; nI < 4; nI++) {
            int colL = warp_n + nI * 8 + cpair;
            int col = c0b + colL;
            float b0 = biasS[colL], b1 = biasS[colL + 1];
            int m = m0 + warp_m + mt * 16 + r0;
            float2 v0 = make_float2(acc[mt][nI][0] + b0, acc[mt][nI][1] + b1);
            float2 v1 = make_float2(acc[mt][nI][2] + b0, acc[mt][nI][3] + b1);
            *(float2*)&g_gatex[(size_t)m * 512 + col] = v0;
            *(float2*)&g_gatex[(size_t)(m + 8) * 512 + col] = v1;
        }
    }
}

// ============================================================
// Kernel 3: persistent LSTM scan, weight loads shared across 2 envs
// ============================================================
#define KS 110
#define SCAN_SMEM_FLOATS (KS * 512 + 256 + 256 + 1024)

__global__ void k_scan(const float* __restrict__ done,
                       const float* __restrict__ h0,
                       const float* __restrict__ c0,
                       float* __restrict__ dout) {
    extern __shared__ float sm[];
    float* Ws = sm;                      // [KS][512]
    float* hs = sm + KS * 512;           // [2][128]
    float* cs = hs + 256;                // [2][128]
    float* gs = cs + 256;                // [2][512]

    int tid = threadIdx.x;
    int e0 = blockIdx.x * 2;

    for (int i = tid; i < KS * 512; i += 256) Ws[i] = g_whhT[i];
    {
        int e = tid >> 7, m = tid & 127;
        int env = e0 + e;
        float s = 1.f - done[env];
        hs[tid] = h0[env * HID + m] * s;
        cs[tid] = c0[env * HID + m] * s;
    }
    __syncthreads();

    int j0 = tid * 2;
    int gtype = tid >> 6;

    for (int t = 0; t < T_STEPS; t++) {
        {
            const float* gxa = g_gatex + (size_t)(t * B_ENV + e0) * NG;
            const float* gxb = gxa + NG;
            float2 a0 = *(const float2*)&gxa[j0];
            float2 b0 = *(const float2*)&gxb[j0];
            float acc00 = a0.x, acc01 = a0.y;
            float acc10 = b0.x, acc11 = b0.y;
            const float* wp = Ws + j0;
            #pragma unroll 10
            for (int k = 0; k < KS; k++) {
                float2 w = *(const float2*)wp;
                float ha = hs[k];
                float hb = hs[128 + k];
                acc00 += w.x * ha; acc01 += w.y * ha;
                acc10 += w.x * hb; acc11 += w.y * hb;
                wp += 512;
            }
            const float* wg = g_whhT + KS * 512 + j0;
            #pragma unroll
            for (int k = KS; k < HID; k++) {
                float2 w = __ldg((const float2*)wg);
                float ha = hs[k];
                float hb = hs[128 + k];
                acc00 += w.x * ha; acc01 += w.y * ha;
                acc10 += w.x * hb; acc11 += w.y * hb;
                wg += 512;
            }
            if (gtype == 2) {
                acc00 = tanhf(acc00); acc01 = tanhf(acc01);
                acc10 = tanhf(acc10); acc11 = tanhf(acc11);
            } else {
                acc00 = 1.f / (1.f + __expf(-acc00));
                acc01 = 1.f / (1.f + __expf(-acc01));
                acc10 = 1.f / (1.f + __expf(-acc10));
                acc11 = 1.f / (1.f + __expf(-acc11));
            }
            gs[j0] = acc00;       gs[j0 + 1] = acc01;
            gs[512 + j0] = acc10; gs[512 + j0 + 1] = acc11;
        }
        __syncthreads();
        {
            int e = tid >> 7, m = tid & 127, env = e0 + e;
            const float* G = gs + e * 512;
            float c = G[128 + m] * cs[tid] + G[m] * G[256 + m];
            float h = G[384 + m] * tanhf(c);
            g_hid[(size_t)(t * B_ENV + env) * HID + m] = h;
            if (t < T_STEPS - 1) {
                float s = 1.f - done[(t + 1) * B_ENV + env];
                hs[tid] = h * s;
                cs[tid] = c * s;
            } else {
                hs[tid] = h;
                cs[tid] = c;
            }
        }
        __syncthreads();
    }

    {
        int e = tid >> 7, m = tid & 127, env = e0 + e;
        dout[262144 + env * HID + m]         = hs[tid];
        dout[262144 + 32768 + env * HID + m] = cs[tid];
    }
}

// ============================================================
// Kernel 4: heads
// ============================================================
__global__ void k_head(const float* __restrict__ aw, const float* __restrict__ ab,
                       const float* __restrict__ cw, const float* __restrict__ cb,
                       float* __restrict__ dout) {
    __shared__ float Hs[32 * 128];
    __shared__ float Wsm[8 * 128];
    __shared__ float Bsm[8];
    int tid = threadIdx.x;
    for (int i = tid; i < 896; i += 256) Wsm[i] = aw[i];
    for (int i = tid; i < 128; i += 256) Wsm[896 + i] = cw[i];
    if (tid < 7) Bsm[tid] = ab[tid];
    if (tid == 7) Bsm[7] = cb[0];
    int n0 = blockIdx.x * 32;
    for (int i = tid; i < 4096; i += 256) Hs[i] = g_hid[(size_t)n0 * 128 + i];
    __syncthreads();
    int r = tid >> 3, o = tid & 7;
    const float* h = Hs + r * 128;
    const float* w = Wsm + o * 128;
    float a = Bsm[o];
    #pragma unroll
    for (int k = 0; k < 128; k++) a += h[k] * w[k];
    dout[(size_t)(n0 + r) * 8 + o] = a;
}

// ============================================================
extern "C" void kernel_launch(void* const* d_in, const int* in_sizes, int n_in,
                              void* d_out, int out_size) {
    const float* obs  = (const float*)d_in[0];
    const float* done = (const float*)d_in[1];
    const float* h0   = (const float*)d_in[2];
    const float* c0   = (const float*)d_in[3];
    const float* w1   = (const float*)d_in[4];
    const float* b1   = (const float*)d_in[5];
    const float* w2   = (const float*)d_in[6];
    const float* b2   = (const float*)d_in[7];
    const float* w3   = (const float*)d_in[8];
    const float* b3   = (const float*)d_in[9];
    const float* wih  = (const float*)d_in[10];
    const float* whh  = (const float*)d_in[11];
    const float* bih  = (const float*)d_in[12];
    const float* bhh  = (const float*)d_in[13];
    const float* aw   = (const float*)d_in[14];
    const float* ab   = (const float*)d_in[15];
    const float* cw   = (const float*)d_in[16];
    const float* cb   = (const float*)d_in[17];
    float* out = (float*)d_out;

    cudaFuncSetAttribute(k_conv, cudaFuncAttributeMaxDynamicSharedMemorySize,
                         (CONV_WSM + 8 * CONV_PW) * 4);
    cudaFuncSetAttribute(k_scan, cudaFuncAttributeMaxDynamicSharedMemorySize,
                         SCAN_SMEM_FLOATS * 4);
    cudaFuncSetAttribute(k_gemm_mma, cudaFuncAttributeMaxDynamicSharedMemorySize,
                         G_TOT);

    k_transpose_whh<<<256, 256>>>(whh);
    k_split_wih<<<2048, 256>>>(wih);
    k_conv<<<4096, 256, (CONV_WSM + 8 * CONV_PW) * 4>>>(obs, w1, b1, w2, b2, w3, b3);
    dim3 gg(256, 8);
    k_gemm_mma<<<gg, 256, G_TOT>>>(bih, bhh);
    k_scan<<<128, 256, SCAN_SMEM_FLOATS * 4>>>(done, h0, c0, out);
    k_head<<<1024, 256>>>(aw, ab, cw, cb, out);
}

// round 5
// speedup vs baseline: 1.5895x; 1.0789x over previous
#include <cuda_runtime.h>
#include <cuda_bf16.h>
#include <math.h>
#include <stdint.h>

#define T_STEPS 128
#define B_ENV   256
#define N_TOT   (T_STEPS * B_ENV)   // 32768
#define HID     128
#define NFLAT   1024
#define NG      512                  // 4*HID

// -------- scratch (static device arrays; no allocation) --------
__device__ float g_gatex[N_TOT * NG];            // 64 MB
__device__ float g_whhT [HID * NG];              // 256 KB
__device__ float g_hid  [N_TOT * HID];           // 16 MB
__device__ __nv_bfloat16 g_featH[N_TOT * NFLAT]; // 64 MB
__device__ __nv_bfloat16 g_featL[N_TOT * NFLAT]; // 64 MB
__device__ __nv_bfloat16 g_wihH [NG * NFLAT];    // 1 MB
__device__ __nv_bfloat16 g_wihL [NG * NFLAT];    // 1 MB

// ================= helpers =================
__device__ __forceinline__ uint32_t s2u(const void* p) {
    uint32_t a;
    asm("{ .reg .u64 t; cvta.to.shared.u64 t, %1; cvt.u32.u64 %0, t; }"
        : "=r"(a) : "l"(p));
    return a;
}
__device__ __forceinline__ void ldsm4(uint32_t* r, uint32_t addr) {
    asm volatile("ldmatrix.sync.aligned.m8n8.x4.shared.b16 {%0,%1,%2,%3}, [%4];"
                 : "=r"(r[0]), "=r"(r[1]), "=r"(r[2]), "=r"(r[3]) : "r"(addr));
}
__device__ __forceinline__ void mma16816(float* d, const uint32_t* a, const uint32_t* b) {
    asm volatile(
        "mma.sync.aligned.m16n8k16.row.col.f32.bf16.bf16.f32 "
        "{%0,%1,%2,%3}, {%4,%5,%6,%7}, {%8,%9}, {%0,%1,%2,%3};"
        : "+f"(d[0]), "+f"(d[1]), "+f"(d[2]), "+f"(d[3])
        : "r"(a[0]), "r"(a[1]), "r"(a[2]), "r"(a[3]), "r"(b[0]), "r"(b[1]));
}
#define CPA16(dst, src) \
    asm volatile("cp.async.cg.shared.global [%0], [%1], 16;" :: "r"(dst), "l"(src))

// ============================================================
// Kernel 0a: transpose w_hh [512,128] -> w_hhT [128,512]
// ============================================================
__global__ void k_transpose_whh(const float* __restrict__ whh) {
    int idx = blockIdx.x * blockDim.x + threadIdx.x;
    if (idx < NG * HID) {
        int k = idx >> 9;
        int j = idx & 511;
        g_whhT[idx] = whh[j * HID + k];
    }
}

// ============================================================
// Kernel 0b: split w_ih into bf16 hi/lo
// ============================================================
__global__ void k_split_wih(const float* __restrict__ wih) {
    int idx = blockIdx.x * blockDim.x + threadIdx.x;
    if (idx < NG * NFLAT) {
        float v = wih[idx];
        __nv_bfloat16 h = __float2bfloat16(v);
        g_wihH[idx] = h;
        g_wihL[idx] = __float2bfloat16(v - __bfloat162float(h));
    }
}

// ============================================================
// Kernel 1: fused conv stack -> feat written as bf16 hi/lo split
// ============================================================
#define CONV_WSM 10544
#define CONV_PW  1523

__global__ void k_conv(const float* __restrict__ obs,
                       const float* __restrict__ w1, const float* __restrict__ b1,
                       const float* __restrict__ w2, const float* __restrict__ b2,
                       const float* __restrict__ w3, const float* __restrict__ b3) {
    extern __shared__ float sm[];
    float* W1 = sm;
    float* B1 = sm + 192;
    float* W2 = sm + 208;
    float* B2 = sm + 2256;
    float* W3 = sm + 2288;
    float* B3 = sm + 10480;
    int tid = threadIdx.x;
    for (int i = tid; i < 192;  i += 256) W1[i] = w1[i];
    for (int i = tid; i < 16;   i += 256) B1[i] = b1[i];
    for (int i = tid; i < 2048; i += 256) W2[i] = w2[i];
    for (int i = tid; i < 32;   i += 256) B2[i] = b2[i];
    for (int i = tid; i < 8192; i += 256) W3[i] = w3[i];
    for (int i = tid; i < 64;   i += 256) B3[i] = b3[i];
    __syncthreads();

    int warp = tid >> 5, lane = tid & 31;
    int n = blockIdx.x * 8 + warp;
    float* buf = sm + CONV_WSM + warp * CONV_PW;
    float* O  = buf;
    float* X1 = buf + 147;
    float* X2 = buf + 723;

    const float* op = obs + (size_t)n * 147;
    for (int i = lane; i < 147; i += 32) O[i] = op[i];
    __syncwarp();

    for (int idx = lane; idx < 576; idx += 32) {
        int co = idx / 36, pos = idx % 36, y = pos / 6, x = pos % 6;
        const float* w = W1 + co * 12;
        float a = B1[co];
        #pragma unroll
        for (int ci = 0; ci < 3; ci++) {
            a += O[(y * 7 + x) * 3 + ci]           * w[ci * 4 + 0];
            a += O[(y * 7 + x + 1) * 3 + ci]       * w[ci * 4 + 1];
            a += O[((y + 1) * 7 + x) * 3 + ci]     * w[ci * 4 + 2];
            a += O[((y + 1) * 7 + x + 1) * 3 + ci] * w[ci * 4 + 3];
        }
        X1[co * 36 + pos] = fmaxf(a, 0.f);
    }
    __syncwarp();

    for (int idx = lane; idx < 800; idx += 32) {
        int co = idx / 25, pos = idx % 25, y = pos / 5, x = pos % 5;
        const float* w = W2 + co * 64;
        float a = B2[co];
        #pragma unroll
        for (int ci = 0; ci < 16; ci++) {
            const float* xp = X1 + ci * 36 + y * 6 + x;
            const float* wp = w + ci * 4;
            a += xp[0] * wp[0] + xp[1] * wp[1] + xp[6] * wp[2] + xp[7] * wp[3];
        }
        X2[co * 25 + pos] = fmaxf(a, 0.f);
    }
    __syncwarp();

    __nv_bfloat16* oh = g_featH + (size_t)n * NFLAT;
    __nv_bfloat16* ol = g_featL + (size_t)n * NFLAT;
    for (int idx = lane; idx < 1024; idx += 32) {
        int co = idx >> 4, y = (idx >> 2) & 3, x = idx & 3;
        const float* w = W3 + co * 128;
        float a = B3[co];
        #pragma unroll
        for (int ci = 0; ci < 32; ci++) {
            const float* xp = X2 + ci * 25 + y * 5 + x;
            const float* wp = w + ci * 4;
            a += xp[0] * wp[0] + xp[1] * wp[1] + xp[5] * wp[2] + xp[6] * wp[3];
        }
        float v = fmaxf(a, 0.f);
        __nv_bfloat16 h = __float2bfloat16(v);
        oh[idx] = h;
        ol[idx] = __float2bfloat16(v - __bfloat162float(h));
    }
}

// ============================================================
// Kernel 2: split-bf16 GEMM via mma.sync (HMMA tensor path)
// grid = (8 col-blocks, 256 row-blocks): a wave covers all col-blocks
// of 37 row-blocks -> A tiles hit L2 7/8 of the time.
// ============================================================
#define RS 80                       // row stride bytes
#define G_AH(buf) (256 + (buf) * 30720)
#define G_AL(buf) (G_AH(buf) + 10240)
#define G_BH(buf) (G_AH(buf) + 20480)
#define G_BL(buf) (G_AH(buf) + 25600)
#define G_TOT (256 + 2 * 30720)     // 61696 bytes

__global__ void __launch_bounds__(256, 2)
k_gemm_mma(const float* __restrict__ bih, const float* __restrict__ bhh) {
    extern __shared__ char smc[];
    uint32_t sb = s2u(smc);
    float* biasS = (float*)smc;
    int tid = threadIdx.x, wid = tid >> 5, lane = tid & 31;
    int m0 = blockIdx.y * 128, c0b = blockIdx.x * 64;   // swapped mapping
    int warp_m = (wid & 3) * 32, warp_n = (wid >> 2) * 32;

    for (int i = tid; i < 64; i += 256) biasS[i] = bih[c0b + i] + bhh[c0b + i];

    int aRow = lane & 15;
    int aKb  = (lane >> 4) * 16;
    int bN   = (lane & 7) + ((lane >> 4) << 3);
    int bKb  = ((lane >> 3) & 1) * 16;

    float acc[2][4][4];
    #pragma unroll
    for (int i = 0; i < 2; i++)
        #pragma unroll
        for (int j = 0; j < 4; j++)
            #pragma unroll
            for (int q = 0; q < 4; q++) acc[i][j][q] = 0.f;

    int arow = tid >> 1, aseg2 = (tid & 1) * 2;
    int brow = tid >> 2, bseg = tid & 3;

    auto load_chunk = [&](int ch, int buf) {
        int k0 = ch * 32;
        const __nv_bfloat16* fH = g_featH + (size_t)(m0 + arow) * 1024 + k0 + aseg2 * 8;
        const __nv_bfloat16* fL = g_featL + (size_t)(m0 + arow) * 1024 + k0 + aseg2 * 8;
        uint32_t da = sb + G_AH(buf) + arow * RS + aseg2 * 16;
        uint32_t dal = sb + G_AL(buf) + arow * RS + aseg2 * 16;
        CPA16(da, fH);      CPA16(da + 16, fH + 8);
        CPA16(dal, fL);     CPA16(dal + 16, fL + 8);
        const __nv_bfloat16* wH = g_wihH + (size_t)(c0b + brow) * 1024 + k0 + bseg * 8;
        const __nv_bfloat16* wL = g_wihL + (size_t)(c0b + brow) * 1024 + k0 + bseg * 8;
        CPA16(sb + G_BH(buf) + brow * RS + bseg * 16, wH);
        CPA16(sb + G_BL(buf) + brow * RS + bseg * 16, wL);
    };

    load_chunk(0, 0);
    asm volatile("cp.async.commit_group;");

    const int NC = 32;
    for (int ch = 0; ch < NC; ch++) {
        int buf = ch & 1;
        if (ch + 1 < NC) {
            load_chunk(ch + 1, buf ^ 1);
            asm volatile("cp.async.commit_group;");
            asm volatile("cp.async.wait_group 1;");
        } else {
            asm volatile("cp.async.wait_group 0;");
        }
        __syncthreads();

        uint32_t aBh = sb + G_AH(buf) + (warp_m + aRow) * RS + aKb;
        uint32_t aBl = sb + G_AL(buf) + (warp_m + aRow) * RS + aKb;
        uint32_t bBh = sb + G_BH(buf) + (warp_n + bN) * RS + bKb;
        uint32_t bBl = sb + G_BL(buf) + (warp_n + bN) * RS + bKb;

        #pragma unroll
        for (int ks = 0; ks < 2; ks++) {
            uint32_t ah[2][4], al[2][4], bh[2][4], bl[2][4];
            #pragma unroll
            for (int mt = 0; mt < 2; mt++) {
                ldsm4(ah[mt], aBh + mt * 16 * RS + ks * 32);
                ldsm4(al[mt], aBl + mt * 16 * RS + ks * 32);
            }
            #pragma unroll
            for (int nt = 0; nt < 2; nt++) {
                ldsm4(bh[nt], bBh + nt * 16 * RS + ks * 32);
                ldsm4(bl[nt], bBl + nt * 16 * RS + ks * 32);
            }
            #pragma unroll
            for (int mt = 0; mt < 2; mt++)
                #pragma unroll
                for (int nt = 0; nt < 2; nt++)
                    #pragma unroll
                    for (int f = 0; f < 2; f++) {
                        float* d = acc[mt][nt * 2 + f];
                        mma16816(d, ah[mt], &bh[nt][f * 2]);
                        mma16816(d, ah[mt], &bl[nt][f * 2]);
                        mma16816(d, al[mt], &bh[nt][f * 2]);
                    }
        }
        __syncthreads();
    }

    int r0 = lane >> 2, cpair = (lane & 3) * 2;
    #pragma unroll
    for (int mt = 0; mt < 2; mt++) {
        #pragma unroll
        for (int nI = 0; nI < 4; nI++) {
            int colL = warp_n + nI * 8 + cpair;
            int col = c0b + colL;
            float b0 = biasS[colL], b1 = biasS[colL + 1];
            int m = m0 + warp_m + mt * 16 + r0;
            float2 v0 = make_float2(acc[mt][nI][0] + b0, acc[mt][nI][1] + b1);
            float2 v1 = make_float2(acc[mt][nI][2] + b0, acc[mt][nI][3] + b1);
            *(float2*)&g_gatex[(size_t)m * 512 + col] = v0;
            *(float2*)&g_gatex[(size_t)(m + 8) * 512 + col] = v1;
        }
    }
}

// ============================================================
// Kernel 3: persistent LSTM scan, 512 threads, split-K halves.
// Lower half (tid<256): cols 2t,2t+1, k in [0,64), + gx init.
// Upper half: same cols, k in [64,108) smem + [108,128) L2,
// partials combined by lower half before activation.
// ============================================================
#define KSW 108
#define KSPLIT 64
#define SCAN_SMEM_FLOATS (KSW * 512 + 256 + 256 + 1024 + 1024)

__global__ void __launch_bounds__(512, 1)
k_scan(const float* __restrict__ done,
       const float* __restrict__ h0,
       const float* __restrict__ c0,
       float* __restrict__ dout) {
    extern __shared__ float sm[];
    float* Ws = sm;                      // [KSW][512]
    float* hs = sm + KSW * 512;          // [2][128]
    float* cs = hs + 256;                // [2][128]
    float* gs = cs + 256;                // [2][512]
    float4* ps = (float4*)(gs + 1024);   // [256] partials (4 floats each)

    int tid = threadIdx.x;
    int tid2 = tid & 255;
    int half = tid >> 8;
    int e0 = blockIdx.x * 2;

    for (int i = tid; i < KSW * 512; i += 512) Ws[i] = g_whhT[i];
    if (tid < 256) {
        int e = tid >> 7, m = tid & 127;
        int env = e0 + e;
        float s = 1.f - done[env];
        hs[tid] = h0[env * HID + m] * s;
        cs[tid] = c0[env * HID + m] * s;
    }
    __syncthreads();

    int j0 = tid2 * 2;
    int gtype = tid2 >> 6;

    for (int t = 0; t < T_STEPS; t++) {
        if (half == 0) {
            // ---- lower: gx + k in [0,KSPLIT) ----
            const float* gxa = g_gatex + (size_t)(t * B_ENV + e0) * NG;
            const float* gxb = gxa + NG;
            float2 a0 = *(const float2*)&gxa[j0];
            float2 b0 = *(const float2*)&gxb[j0];
            float acc00 = a0.x, acc01 = a0.y;
            float acc10 = b0.x, acc11 = b0.y;
            const float* wp = Ws + j0;
            #pragma unroll 8
            for (int k = 0; k < KSPLIT; k++) {
                float2 w = *(const float2*)wp;
                float ha = hs[k];
                float hb = hs[128 + k];
                acc00 += w.x * ha; acc01 += w.y * ha;
                acc10 += w.x * hb; acc11 += w.y * hb;
                wp += 512;
            }
            __syncthreads();   // wait for upper partials
            float4 p = ps[tid2];
            acc00 += p.x; acc01 += p.y; acc10 += p.z; acc11 += p.w;
            if (gtype == 2) {
                acc00 = tanhf(acc00); acc01 = tanhf(acc01);
                acc10 = tanhf(acc10); acc11 = tanhf(acc11);
            } else {
                acc00 = 1.f / (1.f + __expf(-acc00));
                acc01 = 1.f / (1.f + __expf(-acc01));
                acc10 = 1.f / (1.f + __expf(-acc10));
                acc11 = 1.f / (1.f + __expf(-acc11));
            }
            gs[j0] = acc00;       gs[j0 + 1] = acc01;
            gs[512 + j0] = acc10; gs[512 + j0 + 1] = acc11;
        } else {
            // ---- upper: k in [KSPLIT,KSW) smem + [KSW,128) L2 ----
            float acc00 = 0.f, acc01 = 0.f, acc10 = 0.f, acc11 = 0.f;
            const float* wp = Ws + KSPLIT * 512 + j0;
            #pragma unroll 8
            for (int k = KSPLIT; k < KSW; k++) {
                float2 w = *(const float2*)wp;
                float ha = hs[k];
                float hb = hs[128 + k];
                acc00 += w.x * ha; acc01 += w.y * ha;
                acc10 += w.x * hb; acc11 += w.y * hb;
                wp += 512;
            }
            const float* wg = g_whhT + KSW * 512 + j0;
            #pragma unroll
            for (int k = KSW; k < HID; k++) {
                float2 w = __ldg((const float2*)wg);
                float ha = hs[k];
                float hb = hs[128 + k];
                acc00 += w.x * ha; acc01 += w.y * ha;
                acc10 += w.x * hb; acc11 += w.y * hb;
                wg += 512;
            }
            ps[tid2] = make_float4(acc00, acc01, acc10, acc11);
            __syncthreads();   // partials ready
        }
        __syncthreads();       // gates ready
        if (tid < 256) {
            int e = tid >> 7, m = tid & 127, env = e0 + e;
            const float* G = gs + e * 512;
            float c = G[128 + m] * cs[tid] + G[m] * G[256 + m];
            float h = G[384 + m] * tanhf(c);
            g_hid[(size_t)(t * B_ENV + env) * HID + m] = h;
            if (t < T_STEPS - 1) {
                float s = 1.f - done[(t + 1) * B_ENV + env];
                hs[tid] = h * s;
                cs[tid] = c * s;
            } else {
                hs[tid] = h;
                cs[tid] = c;
            }
        }
        __syncthreads();       // h/c ready for next step
    }

    if (tid < 256) {
        int e = tid >> 7, m = tid & 127, env = e0 + e;
        dout[262144 + env * HID + m]         = hs[tid];
        dout[262144 + 32768 + env * HID + m] = cs[tid];
    }
}

// ============================================================
// Kernel 4: heads
// ============================================================
__global__ void k_head(const float* __restrict__ aw, const float* __restrict__ ab,
                       const float* __restrict__ cw, const float* __restrict__ cb,
                       float* __restrict__ dout) {
    __shared__ float Hs[32 * 128];
    __shared__ float Wsm[8 * 128];
    __shared__ float Bsm[8];
    int tid = threadIdx.x;
    for (int i = tid; i < 896; i += 256) Wsm[i] = aw[i];
    for (int i = tid; i < 128; i += 256) Wsm[896 + i] = cw[i];
    if (tid < 7) Bsm[tid] = ab[tid];
    if (tid == 7) Bsm[7] = cb[0];
    int n0 = blockIdx.x * 32;
    for (int i = tid; i < 4096; i += 256) Hs[i] = g_hid[(size_t)n0 * 128 + i];
    __syncthreads();
    int r = tid >> 3, o = tid & 7;
    const float* h = Hs + r * 128;
    const float* w = Wsm + o * 128;
    float a = Bsm[o];
    #pragma unroll
    for (int k = 0; k < 128; k++) a += h[k] * w[k];
    dout[(size_t)(n0 + r) * 8 + o] = a;
}

// ============================================================
extern "C" void kernel_launch(void* const* d_in, const int* in_sizes, int n_in,
                              void* d_out, int out_size) {
    const float* obs  = (const float*)d_in[0];
    const float* done = (const float*)d_in[1];
    const float* h0   = (const float*)d_in[2];
    const float* c0   = (const float*)d_in[3];
    const float* w1   = (const float*)d_in[4];
    const float* b1   = (const float*)d_in[5];
    const float* w2   = (const float*)d_in[6];
    const float* b2   = (const float*)d_in[7];
    const float* w3   = (const float*)d_in[8];
    const float* b3   = (const float*)d_in[9];
    const float* wih  = (const float*)d_in[10];
    const float* whh  = (const float*)d_in[11];
    const float* bih  = (const float*)d_in[12];
    const float* bhh  = (const float*)d_in[13];
    const float* aw   = (const float*)d_in[14];
    const float* ab   = (const float*)d_in[15];
    const float* cw   = (const float*)d_in[16];
    const float* cb   = (const float*)d_in[17];
    float* out = (float*)d_out;

    cudaFuncSetAttribute(k_conv, cudaFuncAttributeMaxDynamicSharedMemorySize,
                         (CONV_WSM + 8 * CONV_PW) * 4);
    cudaFuncSetAttribute(k_scan, cudaFuncAttributeMaxDynamicSharedMemorySize,
                         SCAN_SMEM_FLOATS * 4);
    cudaFuncSetAttribute(k_gemm_mma, cudaFuncAttributeMaxDynamicSharedMemorySize,
                         G_TOT);

    k_transpose_whh<<<256, 256>>>(whh);
    k_split_wih<<<2048, 256>>>(wih);
    k_conv<<<4096, 256, (CONV_WSM + 8 * CONV_PW) * 4>>>(obs, w1, b1, w2, b2, w3, b3);
    dim3 gg(8, 256);
    k_gemm_mma<<<gg, 256, G_TOT>>>(bih, bhh);
    k_scan<<<128, 512, SCAN_SMEM_FLOATS * 4>>>(done, h0, c0, out);
    k_head<<<1024, 256>>>(aw, ab, cw, cb, out);
}

// round 6
// speedup vs baseline: 1.8087x; 1.1379x over previous
#include <cuda_runtime.h>
#include <cuda_bf16.h>
#include <math.h>
#include <stdint.h>

#define T_STEPS 128
#define B_ENV   256
#define N_TOT   (T_STEPS * B_ENV)   // 32768
#define HID     128
#define NFLAT   1024
#define NG      512                  // 4*HID

// -------- scratch (static device arrays; no allocation) --------
__device__ float g_gatex[N_TOT * NG];            // 64 MB
__device__ float g_whhT [HID * NG];              // 256 KB
__device__ float g_hid  [N_TOT * HID];           // 16 MB
__device__ __nv_bfloat16 g_featH[N_TOT * NFLAT]; // 64 MB
__device__ __nv_bfloat16 g_featL[N_TOT * NFLAT]; // 64 MB
__device__ __nv_bfloat16 g_wihH [NG * NFLAT];    // 1 MB
__device__ __nv_bfloat16 g_wihL [NG * NFLAT];    // 1 MB

// ================= helpers =================
__device__ __forceinline__ uint32_t s2u(const void* p) {
    uint32_t a;
    asm("{ .reg .u64 t; cvta.to.shared.u64 t, %1; cvt.u32.u64 %0, t; }"
        : "=r"(a) : "l"(p));
    return a;
}
__device__ __forceinline__ void ldsm4(uint32_t* r, uint32_t addr) {
    asm volatile("ldmatrix.sync.aligned.m8n8.x4.shared.b16 {%0,%1,%2,%3}, [%4];"
                 : "=r"(r[0]), "=r"(r[1]), "=r"(r[2]), "=r"(r[3]) : "r"(addr));
}
__device__ __forceinline__ void mma16816(float* d, const uint32_t* a, const uint32_t* b) {
    asm volatile(
        "mma.sync.aligned.m16n8k16.row.col.f32.bf16.bf16.f32 "
        "{%0,%1,%2,%3}, {%4,%5,%6,%7}, {%8,%9}, {%0,%1,%2,%3};"
        : "+f"(d[0]), "+f"(d[1]), "+f"(d[2]), "+f"(d[3])
        : "r"(a[0]), "r"(a[1]), "r"(a[2]), "r"(a[3]), "r"(b[0]), "r"(b[1]));
}
#define CPA16(dst, src) \
    asm volatile("cp.async.cg.shared.global [%0], [%1], 16;" :: "r"(dst), "l"(src))

// ============================================================
// Kernel 0a: transpose w_hh [512,128] -> w_hhT [128,512]
// ============================================================
__global__ void k_transpose_whh(const float* __restrict__ whh) {
    int idx = blockIdx.x * blockDim.x + threadIdx.x;
    if (idx < NG * HID) {
        int k = idx >> 9;
        int j = idx & 511;
        g_whhT[idx] = whh[j * HID + k];
    }
}

// ============================================================
// Kernel 0b: split w_ih into bf16 hi/lo
// ============================================================
__global__ void k_split_wih(const float* __restrict__ wih) {
    int idx = blockIdx.x * blockDim.x + threadIdx.x;
    if (idx < NG * NFLAT) {
        float v = wih[idx];
        __nv_bfloat16 h = __float2bfloat16(v);
        g_wihH[idx] = h;
        g_wihL[idx] = __float2bfloat16(v - __bfloat162float(h));
    }
}

// ============================================================
// Kernel 1: fused conv stack, register-blocked by output channel.
// One sample per warp. Lanes own channels; accumulators + weights
// + input planes live in registers; smem only for cross-layer tiles.
// ============================================================
#define CONV_WSM 10544
#define CONV_PW  1523

__global__ void __launch_bounds__(256)
k_conv(const float* __restrict__ obs,
       const float* __restrict__ w1, const float* __restrict__ b1,
       const float* __restrict__ w2, const float* __restrict__ b2,
       const float* __restrict__ w3, const float* __restrict__ b3) {
    extern __shared__ float sm[];
    float* W1 = sm;
    float* B1 = sm + 192;
    float* W2 = sm + 208;
    float* B2 = sm + 2256;
    float* W3 = sm + 2288;
    float* B3 = sm + 10480;
    int tid = threadIdx.x;
    for (int i = tid; i < 192;  i += 256) W1[i] = w1[i];
    for (int i = tid; i < 16;   i += 256) B1[i] = b1[i];
    for (int i = tid; i < 2048; i += 256) W2[i] = w2[i];
    for (int i = tid; i < 32;   i += 256) B2[i] = b2[i];
    for (int i = tid; i < 8192; i += 256) W3[i] = w3[i];
    for (int i = tid; i < 64;   i += 256) B3[i] = b3[i];
    __syncthreads();

    int warp = tid >> 5, lane = tid & 31;
    int n = blockIdx.x * 8 + warp;
    float* buf = sm + CONV_WSM + warp * CONV_PW;
    float* O  = buf;          // obs [7][7][3] HWC
    float* X1 = buf + 147;    // [16][6][6]
    float* X2 = buf + 723;    // [32][5][5]

    const float* op = obs + (size_t)n * 147;
    for (int i = lane; i < 147; i += 32) O[i] = op[i];
    __syncwarp();

    // ---- conv1: lane = (ch, row-half). ch in [0,16), half rows ----
    {
        int ch = lane >> 1, half = lane & 1, y0 = half * 3;
        float acc[3][6];
        float bv = B1[ch];
        #pragma unroll
        for (int r = 0; r < 3; r++)
            #pragma unroll
            for (int x = 0; x < 6; x++) acc[r][x] = bv;
        for (int ci = 0; ci < 3; ci++) {
            const float* w = W1 + ch * 12 + ci * 4;
            float w0 = w[0], w1v = w[1], w2v = w[2], w3v = w[3];
            float in[4][7];
            #pragma unroll
            for (int r = 0; r < 4; r++)
                #pragma unroll
                for (int x = 0; x < 7; x++)
                    in[r][x] = O[((y0 + r) * 7 + x) * 3 + ci];
            #pragma unroll
            for (int r = 0; r < 3; r++)
                #pragma unroll
                for (int x = 0; x < 6; x++)
                    acc[r][x] += in[r][x] * w0 + in[r][x + 1] * w1v
                               + in[r + 1][x] * w2v + in[r + 1][x + 1] * w3v;
        }
        #pragma unroll
        for (int r = 0; r < 3; r++)
            #pragma unroll
            for (int x = 0; x < 6; x++)
                X1[ch * 36 + (y0 + r) * 6 + x] = fmaxf(acc[r][x], 0.f);
    }
    __syncwarp();

    // ---- conv2: lane = ch in [0,32). input planes broadcast ----
    {
        int ch = lane;
        float acc[5][5];
        float bv = B2[ch];
        #pragma unroll
        for (int y = 0; y < 5; y++)
            #pragma unroll
            for (int x = 0; x < 5; x++) acc[y][x] = bv;
        for (int ci = 0; ci < 16; ci++) {
            const float* w = W2 + ch * 64 + ci * 4;
            float w0 = w[0], w1v = w[1], w2v = w[2], w3v = w[3];
            float in[6][6];
            const float* xp = X1 + ci * 36;
            #pragma unroll
            for (int y = 0; y < 6; y++)
                #pragma unroll
                for (int x = 0; x < 6; x++) in[y][x] = xp[y * 6 + x];
            #pragma unroll
            for (int y = 0; y < 5; y++)
                #pragma unroll
                for (int x = 0; x < 5; x++)
                    acc[y][x] += in[y][x] * w0 + in[y][x + 1] * w1v
                               + in[y + 1][x] * w2v + in[y + 1][x + 1] * w3v;
        }
        #pragma unroll
        for (int y = 0; y < 5; y++)
            #pragma unroll
            for (int x = 0; x < 5; x++)
                X2[ch * 25 + y * 5 + x] = fmaxf(acc[y][x], 0.f);
    }
    __syncwarp();

    // ---- conv3: lane owns channels (lane, lane+32). planes broadcast ----
    {
        int ca = lane, cb = lane + 32;
        float a0[4][4], a1[4][4];
        float bva = B3[ca], bvb = B3[cb];
        #pragma unroll
        for (int y = 0; y < 4; y++)
            #pragma unroll
            for (int x = 0; x < 4; x++) { a0[y][x] = bva; a1[y][x] = bvb; }
        for (int ci = 0; ci < 32; ci++) {
            const float* wa = W3 + ca * 128 + ci * 4;
            const float* wb = W3 + cb * 128 + ci * 4;
            float wa0 = wa[0], wa1 = wa[1], wa2 = wa[2], wa3 = wa[3];
            float wb0 = wb[0], wb1 = wb[1], wb2 = wb[2], wb3 = wb[3];
            float in[5][5];
            const float* xp = X2 + ci * 25;
            #pragma unroll
            for (int y = 0; y < 5; y++)
                #pragma unroll
                for (int x = 0; x < 5; x++) in[y][x] = xp[y * 5 + x];
            #pragma unroll
            for (int y = 0; y < 4; y++)
                #pragma unroll
                for (int x = 0; x < 4; x++) {
                    a0[y][x] += in[y][x] * wa0 + in[y][x + 1] * wa1
                              + in[y + 1][x] * wa2 + in[y + 1][x + 1] * wa3;
                    a1[y][x] += in[y][x] * wb0 + in[y][x + 1] * wb1
                              + in[y + 1][x] * wb2 + in[y + 1][x + 1] * wb3;
                }
        }
        // stores: feat idx = co*16 + y*4 + x, bf16 hi/lo split, paired
        __nv_bfloat162* ohA = (__nv_bfloat162*)(g_featH + (size_t)n * NFLAT + ca * 16);
        __nv_bfloat162* olA = (__nv_bfloat162*)(g_featL + (size_t)n * NFLAT + ca * 16);
        __nv_bfloat162* ohB = (__nv_bfloat162*)(g_featH + (size_t)n * NFLAT + cb * 16);
        __nv_bfloat162* olB = (__nv_bfloat162*)(g_featL + (size_t)n * NFLAT + cb * 16);
        #pragma unroll
        for (int q = 0; q < 8; q++) {
            int y = q >> 1, x = (q & 1) * 2;
            float v0 = fmaxf(a0[y][x], 0.f), v1 = fmaxf(a0[y][x + 1], 0.f);
            __nv_bfloat16 h0v = __float2bfloat16(v0), h1v = __float2bfloat16(v1);
            ohA[q] = __nv_bfloat162(h0v, h1v);
            olA[q] = __nv_bfloat162(
                __float2bfloat16(v0 - __bfloat162float(h0v)),
                __float2bfloat16(v1 - __bfloat162float(h1v)));
            float u0 = fmaxf(a1[y][x], 0.f), u1 = fmaxf(a1[y][x + 1], 0.f);
            __nv_bfloat16 g0v = __float2bfloat16(u0), g1v = __float2bfloat16(u1);
            ohB[q] = __nv_bfloat162(g0v, g1v);
            olB[q] = __nv_bfloat162(
                __float2bfloat16(u0 - __bfloat162float(g0v)),
                __float2bfloat16(u1 - __bfloat162float(g1v)));
        }
    }
}

// ============================================================
// Kernel 2: split-bf16 GEMM via mma.sync (HMMA tensor path)
// grid = (8 col-blocks, 256 row-blocks) for L2 reuse of A.
// ============================================================
#define RS 80                       // row stride bytes
#define G_AH(buf) (256 + (buf) * 30720)
#define G_AL(buf) (G_AH(buf) + 10240)
#define G_BH(buf) (G_AH(buf) + 20480)
#define G_BL(buf) (G_AH(buf) + 25600)
#define G_TOT (256 + 2 * 30720)     // 61696 bytes

__global__ void __launch_bounds__(256, 2)
k_gemm_mma(const float* __restrict__ bih, const float* __restrict__ bhh) {
    extern __shared__ char smc[];
    uint32_t sb = s2u(smc);
    float* biasS = (float*)smc;
    int tid = threadIdx.x, wid = tid >> 5, lane = tid & 31;
    int m0 = blockIdx.y * 128, c0b = blockIdx.x * 64;
    int warp_m = (wid & 3) * 32, warp_n = (wid >> 2) * 32;

    for (int i = tid; i < 64; i += 256) biasS[i] = bih[c0b + i] + bhh[c0b + i];

    int aRow = lane & 15;
    int aKb  = (lane >> 4) * 16;
    int bN   = (lane & 7) + ((lane >> 4) << 3);
    int bKb  = ((lane >> 3) & 1) * 16;

    float acc[2][4][4];
    #pragma unroll
    for (int i = 0; i < 2; i++)
        #pragma unroll
        for (int j = 0; j < 4; j++)
            #pragma unroll
            for (int q = 0; q < 4; q++) acc[i][j][q] = 0.f;

    int arow = tid >> 1, aseg2 = (tid & 1) * 2;
    int brow = tid >> 2, bseg = tid & 3;

    auto load_chunk = [&](int ch, int buf) {
        int k0 = ch * 32;
        const __nv_bfloat16* fH = g_featH + (size_t)(m0 + arow) * 1024 + k0 + aseg2 * 8;
        const __nv_bfloat16* fL = g_featL + (size_t)(m0 + arow) * 1024 + k0 + aseg2 * 8;
        uint32_t da = sb + G_AH(buf) + arow * RS + aseg2 * 16;
        uint32_t dal = sb + G_AL(buf) + arow * RS + aseg2 * 16;
        CPA16(da, fH);      CPA16(da + 16, fH + 8);
        CPA16(dal, fL);     CPA16(dal + 16, fL + 8);
        const __nv_bfloat16* wH = g_wihH + (size_t)(c0b + brow) * 1024 + k0 + bseg * 8;
        const __nv_bfloat16* wL = g_wihL + (size_t)(c0b + brow) * 1024 + k0 + bseg * 8;
        CPA16(sb + G_BH(buf) + brow * RS + bseg * 16, wH);
        CPA16(sb + G_BL(buf) + brow * RS + bseg * 16, wL);
    };

    load_chunk(0, 0);
    asm volatile("cp.async.commit_group;");

    const int NC = 32;
    for (int ch = 0; ch < NC; ch++) {
        int buf = ch & 1;
        if (ch + 1 < NC) {
            load_chunk(ch + 1, buf ^ 1);
            asm volatile("cp.async.commit_group;");
            asm volatile("cp.async.wait_group 1;");
        } else {
            asm volatile("cp.async.wait_group 0;");
        }
        __syncthreads();

        uint32_t aBh = sb + G_AH(buf) + (warp_m + aRow) * RS + aKb;
        uint32_t aBl = sb + G_AL(buf) + (warp_m + aRow) * RS + aKb;
        uint32_t bBh = sb + G_BH(buf) + (warp_n + bN) * RS + bKb;
        uint32_t bBl = sb + G_BL(buf) + (warp_n + bN) * RS + bKb;

        #pragma unroll
        for (int ks = 0; ks < 2; ks++) {
            uint32_t ah[2][4], al[2][4], bh[2][4], bl[2][4];
            #pragma unroll
            for (int mt = 0; mt < 2; mt++) {
                ldsm4(ah[mt], aBh + mt * 16 * RS + ks * 32);
                ldsm4(al[mt], aBl + mt * 16 * RS + ks * 32);
            }
            #pragma unroll
            for (int nt = 0; nt < 2; nt++) {
                ldsm4(bh[nt], bBh + nt * 16 * RS + ks * 32);
                ldsm4(bl[nt], bBl + nt * 16 * RS + ks * 32);
            }
            #pragma unroll
            for (int mt = 0; mt < 2; mt++)
                #pragma unroll
                for (int nt = 0; nt < 2; nt++)
                    #pragma unroll
                    for (int f = 0; f < 2; f++) {
                        float* d = acc[mt][nt * 2 + f];
                        mma16816(d, ah[mt], &bh[nt][f * 2]);
                        mma16816(d, ah[mt], &bl[nt][f * 2]);
                        mma16816(d, al[mt], &bh[nt][f * 2]);
                    }
        }
        __syncthreads();
    }

    int r0 = lane >> 2, cpair = (lane & 3) * 2;
    #pragma unroll
    for (int mt = 0; mt < 2; mt++) {
        #pragma unroll
        for (int nI = 0; nI < 4; nI++) {
            int colL = warp_n + nI * 8 + cpair;
            int col = c0b + colL;
            float b0 = biasS[colL], b1 = biasS[colL + 1];
            int m = m0 + warp_m + mt * 16 + r0;
            float2 v0 = make_float2(acc[mt][nI][0] + b0, acc[mt][nI][1] + b1);
            float2 v1 = make_float2(acc[mt][nI][2] + b0, acc[mt][nI][3] + b1);
            *(float2*)&g_gatex[(size_t)m * 512 + col] = v0;
            *(float2*)&g_gatex[(size_t)(m + 8) * 512 + col] = v1;
        }
    }
}

// ============================================================
// Kernel 3: persistent LSTM scan, 512 threads, split-K halves.
// ============================================================
#define KSW 108
#define KSPLIT 64
#define SCAN_SMEM_FLOATS (KSW * 512 + 256 + 256 + 1024 + 1024)

__global__ void __launch_bounds__(512, 1)
k_scan(const float* __restrict__ done,
       const float* __restrict__ h0,
       const float* __restrict__ c0,
       float* __restrict__ dout) {
    extern __shared__ float sm[];
    float* Ws = sm;                      // [KSW][512]
    float* hs = sm + KSW * 512;          // [2][128]
    float* cs = hs + 256;                // [2][128]
    float* gs = cs + 256;                // [2][512]
    float4* ps = (float4*)(gs + 1024);   // [256] partials

    int tid = threadIdx.x;
    int tid2 = tid & 255;
    int half = tid >> 8;
    int e0 = blockIdx.x * 2;

    for (int i = tid; i < KSW * 512; i += 512) Ws[i] = g_whhT[i];
    if (tid < 256) {
        int e = tid >> 7, m = tid & 127;
        int env = e0 + e;
        float s = 1.f - done[env];
        hs[tid] = h0[env * HID + m] * s;
        cs[tid] = c0[env * HID + m] * s;
    }
    __syncthreads();

    int j0 = tid2 * 2;
    int gtype = tid2 >> 6;

    for (int t = 0; t < T_STEPS; t++) {
        if (half == 0) {
            const float* gxa = g_gatex + (size_t)(t * B_ENV + e0) * NG;
            const float* gxb = gxa + NG;
            float2 a0 = *(const float2*)&gxa[j0];
            float2 b0 = *(const float2*)&gxb[j0];
            float acc00 = a0.x, acc01 = a0.y;
            float acc10 = b0.x, acc11 = b0.y;
            const float* wp = Ws + j0;
            #pragma unroll 8
            for (int k = 0; k < KSPLIT; k++) {
                float2 w = *(const float2*)wp;
                float ha = hs[k];
                float hb = hs[128 + k];
                acc00 += w.x * ha; acc01 += w.y * ha;
                acc10 += w.x * hb; acc11 += w.y * hb;
                wp += 512;
            }
            __syncthreads();
            float4 p = ps[tid2];
            acc00 += p.x; acc01 += p.y; acc10 += p.z; acc11 += p.w;
            if (gtype == 2) {
                acc00 = tanhf(acc00); acc01 = tanhf(acc01);
                acc10 = tanhf(acc10); acc11 = tanhf(acc11);
            } else {
                acc00 = 1.f / (1.f + __expf(-acc00));
                acc01 = 1.f / (1.f + __expf(-acc01));
                acc10 = 1.f / (1.f + __expf(-acc10));
                acc11 = 1.f / (1.f + __expf(-acc11));
            }
            gs[j0] = acc00;       gs[j0 + 1] = acc01;
            gs[512 + j0] = acc10; gs[512 + j0 + 1] = acc11;
        } else {
            float acc00 = 0.f, acc01 = 0.f, acc10 = 0.f, acc11 = 0.f;
            const float* wp = Ws + KSPLIT * 512 + j0;
            #pragma unroll 8
            for (int k = KSPLIT; k < KSW; k++) {
                float2 w = *(const float2*)wp;
                float ha = hs[k];
                float hb = hs[128 + k];
                acc00 += w.x * ha; acc01 += w.y * ha;
                acc10 += w.x * hb; acc11 += w.y * hb;
                wp += 512;
            }
            const float* wg = g_whhT + KSW * 512 + j0;
            #pragma unroll
            for (int k = KSW; k < HID; k++) {
                float2 w = __ldg((const float2*)wg);
                float ha = hs[k];
                float hb = hs[128 + k];
                acc00 += w.x * ha; acc01 += w.y * ha;
                acc10 += w.x * hb; acc11 += w.y * hb;
                wg += 512;
            }
            ps[tid2] = make_float4(acc00, acc01, acc10, acc11);
            __syncthreads();
        }
        __syncthreads();
        if (tid < 256) {
            int e = tid >> 7, m = tid & 127, env = e0 + e;
            const float* G = gs + e * 512;
            float c = G[128 + m] * cs[tid] + G[m] * G[256 + m];
            float h = G[384 + m] * tanhf(c);
            g_hid[(size_t)(t * B_ENV + env) * HID + m] = h;
            if (t < T_STEPS - 1) {
                float s = 1.f - done[(t + 1) * B_ENV + env];
                hs[tid] = h * s;
                cs[tid] = c * s;
            } else {
                hs[tid] = h;
                cs[tid] = c;
            }
        }
        __syncthreads();
    }

    if (tid < 256) {
        int e = tid >> 7, m = tid & 127, env = e0 + e;
        dout[262144 + env * HID + m]         = hs[tid];
        dout[262144 + 32768 + env * HID + m] = cs[tid];
    }
}

// ============================================================
// Kernel 4: heads
// ============================================================
__global__ void k_head(const float* __restrict__ aw, const float* __restrict__ ab,
                       const float* __restrict__ cw, const float* __restrict__ cb,
                       float* __restrict__ dout) {
    __shared__ float Hs[32 * 128];
    __shared__ float Wsm[8 * 128];
    __shared__ float Bsm[8];
    int tid = threadIdx.x;
    for (int i = tid; i < 896; i += 256) Wsm[i] = aw[i];
    for (int i = tid; i < 128; i += 256) Wsm[896 + i] = cw[i];
    if (tid < 7) Bsm[tid] = ab[tid];
    if (tid == 7) Bsm[7] = cb[0];
    int n0 = blockIdx.x * 32;
    for (int i = tid; i < 4096; i += 256) Hs[i] = g_hid[(size_t)n0 * 128 + i];
    __syncthreads();
    int r = tid >> 3, o = tid & 7;
    const float* h = Hs + r * 128;
    const float* w = Wsm + o * 128;
    float a = Bsm[o];
    #pragma unroll
    for (int k = 0; k < 128; k++) a += h[k] * w[k];
    dout[(size_t)(n0 + r) * 8 + o] = a;
}

// ============================================================
extern "C" void kernel_launch(void* const* d_in, const int* in_sizes, int n_in,
                              void* d_out, int out_size) {
    const float* obs  = (const float*)d_in[0];
    const float* done = (const float*)d_in[1];
    const float* h0   = (const float*)d_in[2];
    const float* c0   = (const float*)d_in[3];
    const float* w1   = (const float*)d_in[4];
    const float* b1   = (const float*)d_in[5];
    const float* w2   = (const float*)d_in[6];
    const float* b2   = (const float*)d_in[7];
    const float* w3   = (const float*)d_in[8];
    const float* b3   = (const float*)d_in[9];
    const float* wih  = (const float*)d_in[10];
    const float* whh  = (const float*)d_in[11];
    const float* bih  = (const float*)d_in[12];
    const float* bhh  = (const float*)d_in[13];
    const float* aw   = (const float*)d_in[14];
    const float* ab   = (const float*)d_in[15];
    const float* cw   = (const float*)d_in[16];
    const float* cb   = (const float*)d_in[17];
    float* out = (float*)d_out;

    cudaFuncSetAttribute(k_conv, cudaFuncAttributeMaxDynamicSharedMemorySize,
                         (CONV_WSM + 8 * CONV_PW) * 4);
    cudaFuncSetAttribute(k_scan, cudaFuncAttributeMaxDynamicSharedMemorySize,
                         SCAN_SMEM_FLOATS * 4);
    cudaFuncSetAttribute(k_gemm_mma, cudaFuncAttributeMaxDynamicSharedMemorySize,
                         G_TOT);

    k_transpose_whh<<<256, 256>>>(whh);
    k_split_wih<<<2048, 256>>>(wih);
    k_conv<<<4096, 256, (CONV_WSM + 8 * CONV_PW) * 4>>>(obs, w1, b1, w2, b2, w3, b3);
    dim3 gg(8, 256);
    k_gemm_mma<<<gg, 256, G_TOT>>>(bih, bhh);
    k_scan<<<128, 512, SCAN_SMEM_FLOATS * 4>>>(done, h0, c0, out);
    k_head<<<1024, 256>>>(aw, ab, cw, cb, out);
}